// round 4
// baseline (speedup 1.0000x reference)
#include <cuda_runtime.h>
#include <cstdint>
#include <cstddef>

typedef unsigned int u32;
typedef unsigned long long u64;

// ---------------- problem dims ----------------
#define B_DIM 4096
#define I_DIM 256
#define H_DIM 1024
#define O_DIM 4096   // 4*H
#define MPL   4      // bit planes

// ---------------- static device scratch (no allocations allowed) ----------------
// Weff stored plane-major: [K][MPL][O]
__device__ float   g_weff_ih[(size_t)I_DIM * MPL * O_DIM];      // 16 MB
__device__ float   g_weff_hh[(size_t)H_DIM * MPL * O_DIM];      // 64 MB
__device__ float   g_bq_ih[MPL * O_DIM];
__device__ float   g_nb_ih[MPL * O_DIM];
__device__ float   g_bq_hh[MPL * O_DIM];
__device__ float   g_nb_hh[MPL * O_DIM];
__device__ uint8_t g_nib_in[(size_t)B_DIM * I_DIM];             // 1 MB
__device__ uint8_t g_nib_hx[(size_t)B_DIM * H_DIM];             // 4 MB
__device__ float   g_gates[(size_t)B_DIM * O_DIM];              // 64 MB
__device__ unsigned g_max[4];

// ---------------- threefry2x32 (JAX-exact) ----------------
__host__ __device__ __forceinline__ void threefry2x32(u32 k0, u32 k1, u32 x0, u32 x1,
                                                      u32 &o0, u32 &o1) {
  u32 ks2 = k0 ^ k1 ^ 0x1BD11BDAu;
  x0 += k0; x1 += k1;
#define TF_ROT(r) { x0 += x1; x1 = (x1 << (r)) | (x1 >> (32 - (r))); x1 ^= x0; }
  TF_ROT(13) TF_ROT(15) TF_ROT(26) TF_ROT(6)   x0 += k1;  x1 += ks2 + 1u;
  TF_ROT(17) TF_ROT(29) TF_ROT(16) TF_ROT(24)  x0 += ks2; x1 += k0 + 2u;
  TF_ROT(13) TF_ROT(15) TF_ROT(26) TF_ROT(6)   x0 += k0;  x1 += k1 + 3u;
  TF_ROT(17) TF_ROT(29) TF_ROT(16) TF_ROT(24)  x0 += k1;  x1 += ks2 + 4u;
  TF_ROT(13) TF_ROT(15) TF_ROT(26) TF_ROT(6)   x0 += ks2; x1 += k0 + 5u;
#undef TF_ROT
  o0 = x0; o1 = x1;
}

// ---------------- XLA-exact f32 transcendentals (unfused rn mul/add) --------
__device__ __forceinline__ float xla_log1p(float x) {
  float u = __fadd_rn(x, 1.0f);
  if (u == 1.0f) return x;
  return __fmul_rn(__fdiv_rn(x, __fsub_rn(u, 1.0f)), logf(u));
}

__device__ __forceinline__ float xla_erfinv(float x) {
  float w = -xla_log1p(__fmul_rn(__fmul_rn(-1.0f, x), x));
  float p;
  if (w < 5.0f) {
    w = __fsub_rn(w, 2.5f);
    p = 2.81022636e-08f;
    p = __fadd_rn(__fmul_rn(p, w), 3.43273939e-07f);
    p = __fadd_rn(__fmul_rn(p, w), -3.5233877e-06f);
    p = __fadd_rn(__fmul_rn(p, w), -4.39150654e-06f);
    p = __fadd_rn(__fmul_rn(p, w), 0.00021858087f);
    p = __fadd_rn(__fmul_rn(p, w), -0.00125372503f);
    p = __fadd_rn(__fmul_rn(p, w), -0.00417768164f);
    p = __fadd_rn(__fmul_rn(p, w), 0.246640727f);
    p = __fadd_rn(__fmul_rn(p, w), 1.50140941f);
  } else {
    w = __fsub_rn(sqrtf(w), 3.0f);
    p = -0.000200214257f;
    p = __fadd_rn(__fmul_rn(p, w), 0.000100950558f);
    p = __fadd_rn(__fmul_rn(p, w), 0.00134934322f);
    p = __fadd_rn(__fmul_rn(p, w), -0.00367342844f);
    p = __fadd_rn(__fmul_rn(p, w), 0.00573950773f);
    p = __fadd_rn(__fmul_rn(p, w), -0.0076224613f);
    p = __fadd_rn(__fmul_rn(p, w), 0.00943887047f);
    p = __fadd_rn(__fmul_rn(p, w), 1.00167406f);
    p = __fadd_rn(__fmul_rn(p, w), 2.83297682f);
  }
  return __fmul_rn(p, x);
}

__device__ __forceinline__ float xla_tanh(float x) {
  float ax = fabsf(x);
  if (ax < 0.0004f) return x;
  float xc = fminf(fmaxf(x, -7.90531110763549805f), 7.90531110763549805f);
  float x2 = __fmul_rn(xc, xc);
  float p = -2.76076847742355e-16f;
  p = __fadd_rn(__fmul_rn(p, x2), 2.00018790482477e-13f);
  p = __fadd_rn(__fmul_rn(p, x2), -8.60467152213735e-11f);
  p = __fadd_rn(__fmul_rn(p, x2), 5.12229709037114e-08f);
  p = __fadd_rn(__fmul_rn(p, x2), 1.48572235717979e-05f);
  p = __fadd_rn(__fmul_rn(p, x2), 6.37261928875436e-04f);
  p = __fadd_rn(__fmul_rn(p, x2), 4.89352455891786e-03f);
  p = __fmul_rn(p, xc);
  float q = 1.19825839466702e-06f;
  q = __fadd_rn(__fmul_rn(q, x2), 1.18534705686654e-04f);
  q = __fadd_rn(__fmul_rn(q, x2), 2.26843463243900e-03f);
  q = __fadd_rn(__fmul_rn(q, x2), 4.89352518554385e-03f);
  return __fdiv_rn(p, q);
}

__device__ __forceinline__ float xla_logistic(float x) {
  return __fadd_rn(0.5f, __fmul_rn(0.5f, xla_tanh(__fmul_rn(0.5f, x))));
}

// bits -> N(0,1) exactly as jax.random.normal (float32 path)
__device__ __forceinline__ float bits_to_normal(u32 bits) {
  float u = __uint_as_float((bits >> 9) | 0x3F800000u) - 1.0f;   // [0,1)
  const float lo = __uint_as_float(0xBF7FFFFFu);                 // nextafter(-1,0)
  float v = __fadd_rn(__fmul_rn(u, 2.0f), lo);
  v = fmaxf(v, lo);
  return __fmul_rn(__uint_as_float(0x3FB504F3u) /*sqrt2*/, xla_erfinv(v));
}

// partitionable threefry random_bits: bits[j] = o0 ^ o1 of TF(key, 0, j)
__device__ __forceinline__ u32 jax_bits32(u32 k0, u32 k1, u32 j) {
  u32 o0, o1; threefry2x32(k0, k1, 0u, j, o0, o1);
  return o0 ^ o1;
}

// ---------------- float max encoding for atomicMax ----------------
__device__ __forceinline__ unsigned fenc(float f) {
  unsigned u = __float_as_uint(f);
  return (u & 0x80000000u) ? ~u : (u | 0x80000000u);
}
__device__ __forceinline__ float fdec(unsigned u) {
  return (u & 0x80000000u) ? __uint_as_float(u & 0x7FFFFFFFu) : __uint_as_float(~u);
}

__global__ void k_init_max() {
  if (threadIdx.x < 4) g_max[threadIdx.x] = fenc(-__int_as_float(0x7F800000));
}

__global__ void k_max(const float* __restrict__ x, int n, int slot) {
  float m = -__int_as_float(0x7F800000);
  for (int i = blockIdx.x * blockDim.x + threadIdx.x; i < n; i += gridDim.x * blockDim.x)
    m = fmaxf(m, x[i]);
#pragma unroll
  for (int o = 16; o; o >>= 1) m = fmaxf(m, __shfl_xor_sync(0xFFFFFFFFu, m, o));
  if ((threadIdx.x & 31) == 0) atomicMax(&g_max[slot], fenc(m));
}

// quant(x, 8, 1.0) for weights
__device__ __forceinline__ float quant_w(float x) {
  float xs = fminf(fmaxf(x, -0.9921875f), 0.9921875f);
  return __fmul_rn(__fdiv_rn(rintf(__fmul_rn(xs, 128.0f)), 128.0f), 1.0f);
}

// Weff[k][m][o] = quant(W[m][k][o]) + normal(ctr = src linear)*wmax*0.1
template<int K>
__global__ void k_build_w(const float* __restrict__ W, int n, u32 kk0, u32 kk1,
                          int slot, int which_hh) {
  int j = blockIdx.x * blockDim.x + threadIdx.x;   // dst linear [K][MPL][O]
  if (j >= n) return;
  float* dst = which_hh ? g_weff_hh : g_weff_ih;
  float wmax = fdec(g_max[slot]);
  int k = j >> 14;                 // MPL*O_DIM = 16384
  int rem = j & 16383;
  int m = rem >> 12, o = rem & 4095;
  u32 src = (u32)((m * K + k) * O_DIM + o);        // source linear = PRNG counter
  float nr = bits_to_normal(jax_bits32(kk0, kk1, src));
  dst[j] = __fadd_rn(quant_w(W[src]), __fmul_rn(__fmul_rn(nr, wmax), 0.1f));
}

// biases: bq and nb separate so the (mm + bq) + nb add order matches reference
__global__ void k_build_b(const float* __restrict__ Bsrc, int n, u32 kk0, u32 kk1,
                          int slot, int which_hh) {
  int j = blockIdx.x * blockDim.x + threadIdx.x;
  if (j >= n) return;
  float* bq = which_hh ? g_bq_hh : g_bq_ih;
  float* nb = which_hh ? g_nb_hh : g_nb_ih;
  float bmax = fdec(g_max[slot]);
  bq[j] = quant_w(Bsrc[j]);
  nb[j] = __fmul_rn(__fmul_rn(bits_to_normal(jax_bits32(kk0, kk1, (u32)j)), bmax), 0.1f);
}

// activation -> 4-bit plane nibble
__global__ void k_nib(const float* __restrict__ x, uint8_t* __restrict__ nib, int n,
                      const float* __restrict__ aP, const float* __restrict__ offP) {
  int i = blockIdx.x * blockDim.x + threadIdx.x;
  if (i >= n) return;
  float a = *aP, off = *offP;
  float t = __fdiv_rn(__fadd_rn(fminf(fmaxf(x[i], -a), a), off), __fmul_rn(a, 2.0f));
  float v = rintf(__fmul_rn(15.0f, t));
  nib[i] = (uint8_t)(((int)v) & 15);
}

// ---------------- GEMM: predicated packed adds (lanes = column pairs) --------
// Per lane: bit ? acc = rn(acc + w) : acc  -- bit-identical to reference's
// sequential ascending-k fp32 chain (rn(w*1+acc) / rn(w*0+acc)).
#define BM 64
#define BN 64
#define KC 32

__device__ __forceinline__ void lds_v2u64(u64 &a, u64 &b, u32 addr) {
  asm volatile("ld.shared.v2.b64 {%0,%1}, [%2];" : "=l"(a), "=l"(b) : "r"(addr));
}
// one predicate, two packed adds (both column-pairs of one (row,plane))
__device__ __forceinline__ void pred_add2x2(u64 &a0, u64 &a1, u64 w0, u64 w1, u32 bit) {
  asm volatile("{\n\t"
               ".reg .pred p;\n\t"
               "setp.ne.u32 p, %4, 0;\n\t"
               "@p add.rn.f32x2 %0, %0, %2;\n\t"
               "@p add.rn.f32x2 %1, %1, %3;\n\t"
               "}"
               : "+l"(a0), "+l"(a1) : "l"(w0), "l"(w1), "r"(bit));
}
__device__ __forceinline__ void unpack2(u64 v, float &lo, float &hi) {
  u32 l, h;
  asm volatile("mov.b64 {%0,%1}, %2;" : "=r"(l), "=r"(h) : "l"(v));
  lo = __uint_as_float(l); hi = __uint_as_float(h);
}

template<int K, bool SECOND>
__launch_bounds__(256, 2)
__global__ void k_gemm(const float* __restrict__ aP) {
  const float* __restrict__ Wg = SECOND ? g_weff_hh : g_weff_ih;   // [K][MPL][O]
  const float* __restrict__ bq = SECOND ? g_bq_hh : g_bq_ih;
  const float* __restrict__ nb = SECOND ? g_nb_hh : g_nb_ih;
  const uint8_t* __restrict__ nibp = SECOND ? g_nib_hx : g_nib_in;

  __shared__ __align__(16) float sW[KC][MPL][BN];   // 32 KB
  __shared__ u32 sA[BM][KC / 4];                    // 2 KB

  int tid = threadIdx.x;
  int tx = tid & 15, ty = tid >> 4;
  int ob = blockIdx.x * BN, bb = blockIdx.y * BM;
  int rowBase = ty * 4;

  u32 sWb = (u32)__cvta_generic_to_shared(sW);

  u64 acc[4][MPL][2];   // [row][plane][col-pair]; lanes = (col, col+1)
#pragma unroll
  for (int r = 0; r < 4; ++r)
#pragma unroll
    for (int m = 0; m < MPL; ++m) { acc[r][m][0] = 0ull; acc[r][m][1] = 0ull; }

  for (int k0 = 0; k0 < K; k0 += KC) {
#pragma unroll
    for (int t = 0; t < 2; ++t) {               // A tile: 64 rows x 8 u32
      int idx = tid + t * 256;
      int r = idx >> 3, k4 = idx & 7;
      sA[r][k4] = *(const u32*)(nibp + (size_t)(bb + r) * K + k0 + k4 * 4);
    }
#pragma unroll
    for (int t = 0; t < 8; ++t) {               // W tile: 2048 float4 copies
      int idx = tid + t * 256;
      int row = idx >> 4;                       // (k*MPL + m), 128 rows
      int q = idx & 15;                         // float4 within row
      *(float4*)((float*)sW + row * BN + q * 4) =
          *(const float4*)(Wg + ((size_t)(k0 + (row >> 2)) * MPL + (row & 3)) * O_DIM
                           + ob + q * 4);
    }
    __syncthreads();

#pragma unroll 2
    for (int k4 = 0; k4 < KC / 4; ++k4) {
      u32 av[4];
#pragma unroll
      for (int r = 0; r < 4; ++r) av[r] = sA[rowBase + r][k4];
#pragma unroll
      for (int s = 0; s < 4; ++s) {
        int k = k4 * 4 + s;
        u64 w[MPL][2];
#pragma unroll
        for (int m = 0; m < MPL; ++m)
          lds_v2u64(w[m][0], w[m][1],
                    sWb + (u32)(((k * MPL + m) * BN + tx * 4) * 4));
#pragma unroll
        for (int r = 0; r < 4; ++r) {
#pragma unroll
          for (int m = 0; m < MPL; ++m) {
            u32 bit = av[r] & (1u << (8 * s + 3 - m));   // plane m <-> nibble bit 3-m
            pred_add2x2(acc[r][m][0], acc[r][m][1], w[m][0], w[m][1], bit);
          }
        }
      }
    }
    __syncthreads();
  }

  // epilogue: threshold per plane, beta-recombine, scale; add part2 if SECOND
  float a = *aP;
  float twoa = __fmul_rn(a, 2.0f);
  const float beta[MPL] = {8.0f / 15.0f, 4.0f / 15.0f, 2.0f / 15.0f, 1.0f / 15.0f};
#pragma unroll
  for (int r = 0; r < 4; ++r) {
#pragma unroll
    for (int c = 0; c < 4; ++c) {
      int b = bb + rowBase + r, o = ob + tx * 4 + c;
      float p = 0.0f;
#pragma unroll
      for (int m = 0; m < MPL; ++m) {
        float lo, hi;
        unpack2(acc[r][m][c >> 1], lo, hi);
        float sv = (c & 1) ? hi : lo;
        float s = __fadd_rn(__fadd_rn(sv, bq[m * O_DIM + o]), nb[m * O_DIM + o]);
        p = __fadd_rn(p, (s > 0.5f) ? beta[m] : 0.0f);
      }
      float part = __fsub_rn(__fmul_rn(p, twoa), a);
      size_t gi = (size_t)b * O_DIM + o;
      if (SECOND) g_gates[gi] = __fadd_rn(g_gates[gi], part);
      else        g_gates[gi] = part;
    }
  }
}

// ---------------- quantized LSTM pointwise tail ----------------
__device__ __forceinline__ float pactf(float x, float a) { return fminf(fmaxf(x, -a), a); }
__device__ __forceinline__ float quant8(float x, float r) {
  float xs = __fdiv_rn(x, r);
  xs = fminf(fmaxf(xs, -0.9921875f), 0.9921875f);
  return __fmul_rn(__fdiv_rn(rintf(__fmul_rn(xs, 128.0f)), 128.0f), r);
}

__global__ void k_lstm(const float* __restrict__ cx, float* __restrict__ out,
                       const float* a3, const float* a4, const float* a5, const float* a6,
                       const float* a7, const float* a8, const float* a9, const float* a10,
                       const float* a11) {
  int idx = blockIdx.x * blockDim.x + threadIdx.x;
  if (idx >= B_DIM * H_DIM) return;
  int b = idx >> 10, h = idx & (H_DIM - 1);
  const float* g = g_gates + (size_t)b * O_DIM;
  float gi = g[h], gj = g[h + 1024], gf = g[h + 2048], go = g[h + 3072];

  float v3 = *a3, v4 = *a4, v5 = *a5, v6 = *a6, v7 = *a7, v8 = *a8, v9 = *a9,
        v10 = *a10, v11 = *a11;
  float fg  = quant8(pactf(xla_logistic(gf), v3), v3);
  float ig  = quant8(pactf(xla_logistic(gi), v4), v4);
  float act = quant8(pactf(xla_tanh(gj), v5), v5);
  float og  = quant8(pactf(xla_logistic(go), v6), v6);
  float gated = quant8(pactf(__fmul_rn(cx[idx], fg), v7), v7);
  float actin = quant8(pactf(__fmul_rn(ig, act), v8), v8);
  float newc  = quant8(pactf(__fadd_rn(gated, actin), v9), v9);
  float actc  = quant8(pactf(xla_tanh(newc), v10), v10);
  float newh  = quant8(pactf(__fmul_rn(actc, og), v11), v11);
  out[idx] = newh;
  out[(size_t)B_DIM * H_DIM + idx] = newc;
}

// ---------------- host side ----------------
static void split2(const u32 k[2], u32 ka[2], u32 kb[2]) {
  threefry2x32(k[0], k[1], 0u, 0u, ka[0], ka[1]);
  threefry2x32(k[0], k[1], 0u, 1u, kb[0], kb[1]);
}

extern "C" void kernel_launch(void* const* d_in, const int* in_sizes, int n_in,
                              void* d_out, int out_size) {
  const float* input = (const float*)d_in[0];
  const float* hx    = (const float*)d_in[1];
  const float* cx    = (const float*)d_in[2];
  const float* wih   = (const float*)d_in[3];
  const float* whh   = (const float*)d_in[4];
  const float* bih   = (const float*)d_in[5];
  const float* bhh   = (const float*)d_in[6];
  const float* a1  = (const float*)d_in[7];
  const float* a3  = (const float*)d_in[8];
  const float* a4  = (const float*)d_in[9];
  const float* a5  = (const float*)d_in[10];
  const float* a6  = (const float*)d_in[11];
  const float* a7  = (const float*)d_in[12];
  const float* a8  = (const float*)d_in[13];
  const float* a9  = (const float*)d_in[14];
  const float* a10 = (const float*)d_in[15];
  const float* a11 = (const float*)d_in[16];

  u32 root[2] = {0u, 42u}, K1[2], K2[2], KW1[2], KB1[2], KW2[2], KB2[2];
  split2(root, K1, K2);
  split2(K1, KW1, KB1);
  split2(K2, KW2, KB2);

  const int n_wih = MPL * I_DIM * O_DIM;   // 4,194,304
  const int n_whh = MPL * H_DIM * O_DIM;   // 16,777,216
  const int n_b   = MPL * O_DIM;           // 16,384

  k_init_max<<<1, 32>>>();
  k_max<<<512, 256>>>(wih, n_wih, 0);
  k_max<<<512, 256>>>(whh, n_whh, 1);
  k_max<<<64, 256>>>(bih, n_b, 2);
  k_max<<<64, 256>>>(bhh, n_b, 3);

  k_build_w<I_DIM><<<(n_wih + 255) / 256, 256>>>(wih, n_wih, KW1[0], KW1[1], 0, 0);
  k_build_w<H_DIM><<<(n_whh + 255) / 256, 256>>>(whh, n_whh, KW2[0], KW2[1], 1, 1);
  k_build_b<<<(n_b + 255) / 256, 256>>>(bih, n_b, KB1[0], KB1[1], 2, 0);
  k_build_b<<<(n_b + 255) / 256, 256>>>(bhh, n_b, KB2[0], KB2[1], 3, 1);

  {
    uint8_t* nin; cudaGetSymbolAddress((void**)&nin, g_nib_in);
    uint8_t* nhx; cudaGetSymbolAddress((void**)&nhx, g_nib_hx);
    k_nib<<<(B_DIM * I_DIM + 255) / 256, 256>>>(input, nin, B_DIM * I_DIM, a1, a1);
    k_nib<<<(B_DIM * H_DIM + 255) / 256, 256>>>(hx, nhx, B_DIM * H_DIM, a11, a1);
  }

  dim3 gg(O_DIM / BN, B_DIM / BM);
  k_gemm<I_DIM, false><<<gg, 256>>>(a1);    // part1 -> g_gates
  k_gemm<H_DIM, true><<<gg, 256>>>(a11);    // g_gates += part2

  k_lstm<<<(B_DIM * H_DIM + 255) / 256, 256>>>(cx, (float*)d_out,
                                               a3, a4, a5, a6, a7, a8, a9, a10, a11);
}

// round 5
// speedup vs baseline: 1.1418x; 1.1418x over previous
#include <cuda_runtime.h>
#include <cstdint>
#include <cstddef>

typedef unsigned int u32;
typedef unsigned long long u64;

// ---------------- problem dims ----------------
#define B_DIM 4096
#define I_DIM 256
#define H_DIM 1024
#define O_DIM 4096   // 4*H
#define MPL   4      // bit planes

// ---------------- static device scratch (no allocations allowed) ----------------
// Weff stored plane-interleaved: [K][O][MPL]
__device__ float   g_weff_ih[(size_t)I_DIM * O_DIM * MPL];      // 16 MB
__device__ float   g_weff_hh[(size_t)H_DIM * O_DIM * MPL];      // 64 MB
__device__ float   g_bq_ih[MPL * O_DIM];
__device__ float   g_nb_ih[MPL * O_DIM];
__device__ float   g_bq_hh[MPL * O_DIM];
__device__ float   g_nb_hh[MPL * O_DIM];
// pre-expanded bit-plane masks: one float4 (plane0..plane3 in {0,1}) per (b,k)
__device__ float4  g_mask_in[(size_t)B_DIM * I_DIM];            // 16 MB
__device__ float4  g_mask_hx[(size_t)B_DIM * H_DIM];            // 64 MB
__device__ float   g_gates[(size_t)B_DIM * O_DIM];              // 64 MB
__device__ unsigned g_max[4];

// ---------------- threefry2x32 (JAX-exact) ----------------
__host__ __device__ __forceinline__ void threefry2x32(u32 k0, u32 k1, u32 x0, u32 x1,
                                                      u32 &o0, u32 &o1) {
  u32 ks2 = k0 ^ k1 ^ 0x1BD11BDAu;
  x0 += k0; x1 += k1;
#define TF_ROT(r) { x0 += x1; x1 = (x1 << (r)) | (x1 >> (32 - (r))); x1 ^= x0; }
  TF_ROT(13) TF_ROT(15) TF_ROT(26) TF_ROT(6)   x0 += k1;  x1 += ks2 + 1u;
  TF_ROT(17) TF_ROT(29) TF_ROT(16) TF_ROT(24)  x0 += ks2; x1 += k0 + 2u;
  TF_ROT(13) TF_ROT(15) TF_ROT(26) TF_ROT(6)   x0 += k0;  x1 += k1 + 3u;
  TF_ROT(17) TF_ROT(29) TF_ROT(16) TF_ROT(24)  x0 += k1;  x1 += ks2 + 4u;
  TF_ROT(13) TF_ROT(15) TF_ROT(26) TF_ROT(6)   x0 += ks2; x1 += k0 + 5u;
#undef TF_ROT
  o0 = x0; o1 = x1;
}

// ---------------- XLA-exact f32 transcendentals (unfused rn mul/add) --------
__device__ __forceinline__ float xla_log1p(float x) {
  float u = __fadd_rn(x, 1.0f);
  if (u == 1.0f) return x;
  return __fmul_rn(__fdiv_rn(x, __fsub_rn(u, 1.0f)), logf(u));
}

__device__ __forceinline__ float xla_erfinv(float x) {
  float w = -xla_log1p(__fmul_rn(__fmul_rn(-1.0f, x), x));
  float p;
  if (w < 5.0f) {
    w = __fsub_rn(w, 2.5f);
    p = 2.81022636e-08f;
    p = __fadd_rn(__fmul_rn(p, w), 3.43273939e-07f);
    p = __fadd_rn(__fmul_rn(p, w), -3.5233877e-06f);
    p = __fadd_rn(__fmul_rn(p, w), -4.39150654e-06f);
    p = __fadd_rn(__fmul_rn(p, w), 0.00021858087f);
    p = __fadd_rn(__fmul_rn(p, w), -0.00125372503f);
    p = __fadd_rn(__fmul_rn(p, w), -0.00417768164f);
    p = __fadd_rn(__fmul_rn(p, w), 0.246640727f);
    p = __fadd_rn(__fmul_rn(p, w), 1.50140941f);
  } else {
    w = __fsub_rn(sqrtf(w), 3.0f);
    p = -0.000200214257f;
    p = __fadd_rn(__fmul_rn(p, w), 0.000100950558f);
    p = __fadd_rn(__fmul_rn(p, w), 0.00134934322f);
    p = __fadd_rn(__fmul_rn(p, w), -0.00367342844f);
    p = __fadd_rn(__fmul_rn(p, w), 0.00573950773f);
    p = __fadd_rn(__fmul_rn(p, w), -0.0076224613f);
    p = __fadd_rn(__fmul_rn(p, w), 0.00943887047f);
    p = __fadd_rn(__fmul_rn(p, w), 1.00167406f);
    p = __fadd_rn(__fmul_rn(p, w), 2.83297682f);
  }
  return __fmul_rn(p, x);
}

__device__ __forceinline__ float xla_tanh(float x) {
  float ax = fabsf(x);
  if (ax < 0.0004f) return x;
  float xc = fminf(fmaxf(x, -7.90531110763549805f), 7.90531110763549805f);
  float x2 = __fmul_rn(xc, xc);
  float p = -2.76076847742355e-16f;
  p = __fadd_rn(__fmul_rn(p, x2), 2.00018790482477e-13f);
  p = __fadd_rn(__fmul_rn(p, x2), -8.60467152213735e-11f);
  p = __fadd_rn(__fmul_rn(p, x2), 5.12229709037114e-08f);
  p = __fadd_rn(__fmul_rn(p, x2), 1.48572235717979e-05f);
  p = __fadd_rn(__fmul_rn(p, x2), 6.37261928875436e-04f);
  p = __fadd_rn(__fmul_rn(p, x2), 4.89352455891786e-03f);
  p = __fmul_rn(p, xc);
  float q = 1.19825839466702e-06f;
  q = __fadd_rn(__fmul_rn(q, x2), 1.18534705686654e-04f);
  q = __fadd_rn(__fmul_rn(q, x2), 2.26843463243900e-03f);
  q = __fadd_rn(__fmul_rn(q, x2), 4.89352518554385e-03f);
  return __fdiv_rn(p, q);
}

__device__ __forceinline__ float xla_logistic(float x) {
  return __fadd_rn(0.5f, __fmul_rn(0.5f, xla_tanh(__fmul_rn(0.5f, x))));
}

// bits -> N(0,1) exactly as jax.random.normal (float32 path)
__device__ __forceinline__ float bits_to_normal(u32 bits) {
  float u = __uint_as_float((bits >> 9) | 0x3F800000u) - 1.0f;   // [0,1)
  const float lo = __uint_as_float(0xBF7FFFFFu);                 // nextafter(-1,0)
  float v = __fadd_rn(__fmul_rn(u, 2.0f), lo);
  v = fmaxf(v, lo);
  return __fmul_rn(__uint_as_float(0x3FB504F3u) /*sqrt2*/, xla_erfinv(v));
}

// partitionable threefry random_bits: bits[j] = o0 ^ o1 of TF(key, 0, j)
__device__ __forceinline__ u32 jax_bits32(u32 k0, u32 k1, u32 j) {
  u32 o0, o1; threefry2x32(k0, k1, 0u, j, o0, o1);
  return o0 ^ o1;
}

// ---------------- float max encoding for atomicMax ----------------
__device__ __forceinline__ unsigned fenc(float f) {
  unsigned u = __float_as_uint(f);
  return (u & 0x80000000u) ? ~u : (u | 0x80000000u);
}
__device__ __forceinline__ float fdec(unsigned u) {
  return (u & 0x80000000u) ? __uint_as_float(u & 0x7FFFFFFFu) : __uint_as_float(~u);
}

__global__ void k_init_max() {
  if (threadIdx.x < 4) g_max[threadIdx.x] = fenc(-__int_as_float(0x7F800000));
}

__global__ void k_max(const float* __restrict__ x, int n, int slot) {
  float m = -__int_as_float(0x7F800000);
  for (int i = blockIdx.x * blockDim.x + threadIdx.x; i < n; i += gridDim.x * blockDim.x)
    m = fmaxf(m, x[i]);
#pragma unroll
  for (int o = 16; o; o >>= 1) m = fmaxf(m, __shfl_xor_sync(0xFFFFFFFFu, m, o));
  if ((threadIdx.x & 31) == 0) atomicMax(&g_max[slot], fenc(m));
}

// quant(x, 8, 1.0) for weights
__device__ __forceinline__ float quant_w(float x) {
  float xs = fminf(fmaxf(x, -0.9921875f), 0.9921875f);
  return __fmul_rn(__fdiv_rn(rintf(__fmul_rn(xs, 128.0f)), 128.0f), 1.0f);
}

// Weff[k][o][m] = quant(W[m][k][o]) + normal(ctr = src linear)*wmax*0.1
template<int K>
__global__ void k_build_w(const float* __restrict__ W, int n, u32 kk0, u32 kk1,
                          int slot, int which_hh) {
  int j = blockIdx.x * blockDim.x + threadIdx.x;   // dst linear [K][O][MPL]
  if (j >= n) return;
  float* dst = which_hh ? g_weff_hh : g_weff_ih;
  float wmax = fdec(g_max[slot]);
  int k = j >> 14;                 // O_DIM*MPL = 16384
  int rem = j & 16383;
  int o = rem >> 2, m = rem & 3;
  u32 src = (u32)((m * K + k) * O_DIM + o);        // source linear = PRNG counter
  float nr = bits_to_normal(jax_bits32(kk0, kk1, src));
  dst[j] = __fadd_rn(quant_w(W[src]), __fmul_rn(__fmul_rn(nr, wmax), 0.1f));
}

// biases: bq and nb separate so the (mm + bq) + nb add order matches reference
__global__ void k_build_b(const float* __restrict__ Bsrc, int n, u32 kk0, u32 kk1,
                          int slot, int which_hh) {
  int j = blockIdx.x * blockDim.x + threadIdx.x;
  if (j >= n) return;
  float* bq = which_hh ? g_bq_hh : g_bq_ih;
  float* nb = which_hh ? g_nb_hh : g_nb_ih;
  float bmax = fdec(g_max[slot]);
  bq[j] = quant_w(Bsrc[j]);
  nb[j] = __fmul_rn(__fmul_rn(bits_to_normal(jax_bits32(kk0, kk1, (u32)j)), bmax), 0.1f);
}

// activation -> expanded bit-plane masks: float4 (plane0..plane3) in {0,1}
__global__ void k_mask(const float* __restrict__ x, float4* __restrict__ mout, int n,
                       const float* __restrict__ aP, const float* __restrict__ offP) {
  int i = blockIdx.x * blockDim.x + threadIdx.x;
  if (i >= n) return;
  float a = *aP, off = *offP;
  float t = __fdiv_rn(__fadd_rn(fminf(fmaxf(x[i], -a), a), off), __fmul_rn(a, 2.0f));
  int v = ((int)rintf(__fmul_rn(15.0f, t))) & 15;
  mout[i] = make_float4((float)((v >> 3) & 1), (float)((v >> 2) & 1),
                        (float)((v >> 1) & 1), (float)(v & 1));
}

// ---------------- GEMM via packed fma.rn.f32x2 (lanes = plane pairs) ----------
// Per-lane: acc = rn(w*mask + acc), mask in {0.0,1.0} -> bit-identical to the
// reference's sequential ascending-k fp32 FFMA chain.
#define BM 64
#define BN 64
#define KC 32
#define MROW 528                      // padded mask row stride (bytes)
#define SW_BYTES (KC * BN * 16)       // 32768
#define SMEM_SZ (SW_BYTES + BM * MROW)  // 32768 + 33792 = 66560

__device__ __forceinline__ void fma2(u64 &acc, u64 w, u64 m) {
  asm volatile("fma.rn.f32x2 %0, %1, %2, %0;" : "+l"(acc) : "l"(w), "l"(m));
}
__device__ __forceinline__ void lds_v2u64(u64 &a, u64 &b, u32 addr) {
  asm volatile("ld.shared.v2.b64 {%0,%1}, [%2];" : "=l"(a), "=l"(b) : "r"(addr));
}
__device__ __forceinline__ void unpack2(u64 v, float &lo, float &hi) {
  u32 l, h;
  asm volatile("mov.b64 {%0,%1}, %2;" : "=r"(l), "=r"(h) : "l"(v));
  lo = __uint_as_float(l); hi = __uint_as_float(h);
}

template<int K, bool SECOND>
__launch_bounds__(256, 2)
__global__ void k_gemm(const float* __restrict__ aP) {
  const float* __restrict__ Wg = SECOND ? g_weff_hh : g_weff_ih;   // [K][O][MPL]
  const float* __restrict__ bq = SECOND ? g_bq_hh : g_bq_ih;
  const float* __restrict__ nb = SECOND ? g_nb_hh : g_nb_ih;
  const float4* __restrict__ Mg = SECOND ? g_mask_hx : g_mask_in;  // [B][K]

  extern __shared__ __align__(16) char smem[];
  float* sW = (float*)smem;                 // [KC][BN][4] = 32 KB
  char*  sM = smem + SW_BYTES;              // [BM][MROW]  = 33 KB

  int tid = threadIdx.x;
  int tx = tid & 15, ty = tid >> 4;
  int ob = blockIdx.x * BN, bb = blockIdx.y * BM;
  int rowBase = ty * 4;

  u32 sWb = (u32)__cvta_generic_to_shared(sW);
  u32 sMb = (u32)__cvta_generic_to_shared(sM);

  u64 acc[4][4][2];   // [row][col][plane-pair]
#pragma unroll
  for (int r = 0; r < 4; ++r)
#pragma unroll
    for (int c = 0; c < 4; ++c) { acc[r][c][0] = 0ull; acc[r][c][1] = 0ull; }

  for (int k0 = 0; k0 < K; k0 += KC) {
#pragma unroll
    for (int t = 0; t < 8; ++t) {               // mask tile: 64 rows x 32 k x 16B
      int idx = tid + t * 256;
      int r = idx >> 5, k = idx & 31;
      float4 v = Mg[(size_t)(bb + r) * K + k0 + k];
      *(float4*)(sM + r * MROW + k * 16) = v;
    }
#pragma unroll
    for (int t = 0; t < 8; ++t) {               // W tile: 2048 contiguous float4
      int idx = tid + t * 256;
      int k = idx >> 6, o = idx & 63;
      *(float4*)(sW + (k * BN + o) * 4) =
          *(const float4*)(Wg + ((size_t)(k0 + k) * O_DIM + ob + o) * 4);
    }
    __syncthreads();

#pragma unroll 4
    for (int k = 0; k < KC; ++k) {
      u64 mk[4][2];
#pragma unroll
      for (int r = 0; r < 4; ++r)
        lds_v2u64(mk[r][0], mk[r][1], sMb + (u32)((rowBase + r) * MROW + k * 16));
#pragma unroll
      for (int c = 0; c < 4; ++c) {
        u64 w0, w1;
        lds_v2u64(w0, w1, sWb + (u32)((k * BN + tx + 16 * c) * 16));
#pragma unroll
        for (int r = 0; r < 4; ++r) {
          fma2(acc[r][c][0], w0, mk[r][0]);
          fma2(acc[r][c][1], w1, mk[r][1]);
        }
      }
    }
    __syncthreads();
  }

  // epilogue: threshold per plane, beta-recombine, scale; add part2 if SECOND
  float a = *aP;
  float twoa = __fmul_rn(a, 2.0f);
  const float beta[MPL] = {8.0f / 15.0f, 4.0f / 15.0f, 2.0f / 15.0f, 1.0f / 15.0f};
#pragma unroll
  for (int r = 0; r < 4; ++r) {
#pragma unroll
    for (int c = 0; c < 4; ++c) {
      int b = bb + rowBase + r, o = ob + tx + 16 * c;
      float sv[4];
      unpack2(acc[r][c][0], sv[0], sv[1]);
      unpack2(acc[r][c][1], sv[2], sv[3]);
      float p = 0.0f;
#pragma unroll
      for (int m = 0; m < MPL; ++m) {
        float s = __fadd_rn(__fadd_rn(sv[m], bq[m * O_DIM + o]), nb[m * O_DIM + o]);
        p = __fadd_rn(p, (s > 0.5f) ? beta[m] : 0.0f);
      }
      float part = __fsub_rn(__fmul_rn(p, twoa), a);
      size_t gi = (size_t)b * O_DIM + o;
      if (SECOND) g_gates[gi] = __fadd_rn(g_gates[gi], part);
      else        g_gates[gi] = part;
    }
  }
}

// ---------------- quantized LSTM pointwise tail ----------------
__device__ __forceinline__ float pactf(float x, float a) { return fminf(fmaxf(x, -a), a); }
__device__ __forceinline__ float quant8(float x, float r) {
  float xs = __fdiv_rn(x, r);
  xs = fminf(fmaxf(xs, -0.9921875f), 0.9921875f);
  return __fmul_rn(__fdiv_rn(rintf(__fmul_rn(xs, 128.0f)), 128.0f), r);
}

__global__ void k_lstm(const float* __restrict__ cx, float* __restrict__ out,
                       const float* a3, const float* a4, const float* a5, const float* a6,
                       const float* a7, const float* a8, const float* a9, const float* a10,
                       const float* a11) {
  int idx = blockIdx.x * blockDim.x + threadIdx.x;
  if (idx >= B_DIM * H_DIM) return;
  int b = idx >> 10, h = idx & (H_DIM - 1);
  const float* g = g_gates + (size_t)b * O_DIM;
  float gi = g[h], gj = g[h + 1024], gf = g[h + 2048], go = g[h + 3072];

  float v3 = *a3, v4 = *a4, v5 = *a5, v6 = *a6, v7 = *a7, v8 = *a8, v9 = *a9,
        v10 = *a10, v11 = *a11;
  float fg  = quant8(pactf(xla_logistic(gf), v3), v3);
  float ig  = quant8(pactf(xla_logistic(gi), v4), v4);
  float act = quant8(pactf(xla_tanh(gj), v5), v5);
  float og  = quant8(pactf(xla_logistic(go), v6), v6);
  float gated = quant8(pactf(__fmul_rn(cx[idx], fg), v7), v7);
  float actin = quant8(pactf(__fmul_rn(ig, act), v8), v8);
  float newc  = quant8(pactf(__fadd_rn(gated, actin), v9), v9);
  float actc  = quant8(pactf(xla_tanh(newc), v10), v10);
  float newh  = quant8(pactf(__fmul_rn(actc, og), v11), v11);
  out[idx] = newh;
  out[(size_t)B_DIM * H_DIM + idx] = newc;
}

// ---------------- host side ----------------
static void split2(const u32 k[2], u32 ka[2], u32 kb[2]) {
  threefry2x32(k[0], k[1], 0u, 0u, ka[0], ka[1]);
  threefry2x32(k[0], k[1], 0u, 1u, kb[0], kb[1]);
}

extern "C" void kernel_launch(void* const* d_in, const int* in_sizes, int n_in,
                              void* d_out, int out_size) {
  const float* input = (const float*)d_in[0];
  const float* hx    = (const float*)d_in[1];
  const float* cx    = (const float*)d_in[2];
  const float* wih   = (const float*)d_in[3];
  const float* whh   = (const float*)d_in[4];
  const float* bih   = (const float*)d_in[5];
  const float* bhh   = (const float*)d_in[6];
  const float* a1  = (const float*)d_in[7];
  const float* a3  = (const float*)d_in[8];
  const float* a4  = (const float*)d_in[9];
  const float* a5  = (const float*)d_in[10];
  const float* a6  = (const float*)d_in[11];
  const float* a7  = (const float*)d_in[12];
  const float* a8  = (const float*)d_in[13];
  const float* a9  = (const float*)d_in[14];
  const float* a10 = (const float*)d_in[15];
  const float* a11 = (const float*)d_in[16];

  u32 root[2] = {0u, 42u}, K1[2], K2[2], KW1[2], KB1[2], KW2[2], KB2[2];
  split2(root, K1, K2);
  split2(K1, KW1, KB1);
  split2(K2, KW2, KB2);

  const int n_wih = MPL * I_DIM * O_DIM;   // 4,194,304
  const int n_whh = MPL * H_DIM * O_DIM;   // 16,777,216
  const int n_b   = MPL * O_DIM;           // 16,384

  static bool attr_done = false;
  if (!attr_done) {
    cudaFuncSetAttribute(k_gemm<I_DIM, false>,
                         cudaFuncAttributeMaxDynamicSharedMemorySize, SMEM_SZ);
    cudaFuncSetAttribute(k_gemm<H_DIM, true>,
                         cudaFuncAttributeMaxDynamicSharedMemorySize, SMEM_SZ);
    attr_done = true;
  }

  k_init_max<<<1, 32>>>();
  k_max<<<512, 256>>>(wih, n_wih, 0);
  k_max<<<512, 256>>>(whh, n_whh, 1);
  k_max<<<64, 256>>>(bih, n_b, 2);
  k_max<<<64, 256>>>(bhh, n_b, 3);

  k_build_w<I_DIM><<<(n_wih + 255) / 256, 256>>>(wih, n_wih, KW1[0], KW1[1], 0, 0);
  k_build_w<H_DIM><<<(n_whh + 255) / 256, 256>>>(whh, n_whh, KW2[0], KW2[1], 1, 1);
  k_build_b<<<(n_b + 255) / 256, 256>>>(bih, n_b, KB1[0], KB1[1], 2, 0);
  k_build_b<<<(n_b + 255) / 256, 256>>>(bhh, n_b, KB2[0], KB2[1], 3, 1);

  {
    float4* min_; cudaGetSymbolAddress((void**)&min_, g_mask_in);
    float4* mhx;  cudaGetSymbolAddress((void**)&mhx, g_mask_hx);
    k_mask<<<(B_DIM * I_DIM + 255) / 256, 256>>>(input, min_, B_DIM * I_DIM, a1, a1);
    k_mask<<<(B_DIM * H_DIM + 255) / 256, 256>>>(hx, mhx, B_DIM * H_DIM, a11, a1);
  }

  dim3 gg(O_DIM / BN, B_DIM / BM);
  k_gemm<I_DIM, false><<<gg, 256, SMEM_SZ>>>(a1);    // part1 -> g_gates
  k_gemm<H_DIM, true><<<gg, 256, SMEM_SZ>>>(a11);    // g_gates += part2

  k_lstm<<<(B_DIM * H_DIM + 255) / 256, 256>>>(cx, (float*)d_out,
                                               a3, a4, a5, a6, a7, a8, a9, a10, a11);
}

// round 6
// speedup vs baseline: 1.2841x; 1.1246x over previous
#include <cuda_runtime.h>
#include <cstdint>
#include <cstddef>

typedef unsigned int u32;
typedef unsigned long long u64;

// ---------------- problem dims ----------------
#define B_DIM 4096
#define I_DIM 256
#define H_DIM 1024
#define O_DIM 4096   // 4*H
#define MPL   4      // bit planes

// ---------------- static device scratch (no allocations allowed) ----------------
// Weff stored plane-interleaved: [K][O][MPL]
__device__ float   g_weff_ih[(size_t)I_DIM * O_DIM * MPL];      // 16 MB
__device__ float   g_weff_hh[(size_t)H_DIM * O_DIM * MPL];      // 64 MB
__device__ float   g_bq_ih[MPL * O_DIM];
__device__ float   g_nb_ih[MPL * O_DIM];
__device__ float   g_bq_hh[MPL * O_DIM];
__device__ float   g_nb_hh[MPL * O_DIM];
__device__ uint8_t g_nib_in[(size_t)B_DIM * I_DIM];             // 1 MB
__device__ uint8_t g_nib_hx[(size_t)B_DIM * H_DIM];             // 4 MB
__device__ float   g_gates1[(size_t)B_DIM * O_DIM];             // 64 MB (part1, ih)
__device__ float   g_gates2[(size_t)B_DIM * O_DIM];             // 64 MB (part2, hh)
__device__ unsigned g_max[4];
__device__ unsigned g_tile;                                      // persistent scheduler

// ---------------- threefry2x32 (JAX-exact) ----------------
__host__ __device__ __forceinline__ void threefry2x32(u32 k0, u32 k1, u32 x0, u32 x1,
                                                      u32 &o0, u32 &o1) {
  u32 ks2 = k0 ^ k1 ^ 0x1BD11BDAu;
  x0 += k0; x1 += k1;
#define TF_ROT(r) { x0 += x1; x1 = (x1 << (r)) | (x1 >> (32 - (r))); x1 ^= x0; }
  TF_ROT(13) TF_ROT(15) TF_ROT(26) TF_ROT(6)   x0 += k1;  x1 += ks2 + 1u;
  TF_ROT(17) TF_ROT(29) TF_ROT(16) TF_ROT(24)  x0 += ks2; x1 += k0 + 2u;
  TF_ROT(13) TF_ROT(15) TF_ROT(26) TF_ROT(6)   x0 += k0;  x1 += k1 + 3u;
  TF_ROT(17) TF_ROT(29) TF_ROT(16) TF_ROT(24)  x0 += k1;  x1 += ks2 + 4u;
  TF_ROT(13) TF_ROT(15) TF_ROT(26) TF_ROT(6)   x0 += ks2; x1 += k0 + 5u;
#undef TF_ROT
  o0 = x0; o1 = x1;
}

// ---------------- XLA-exact f32 transcendentals (unfused rn mul/add) --------
__device__ __forceinline__ float xla_log1p(float x) {
  float u = __fadd_rn(x, 1.0f);
  if (u == 1.0f) return x;
  return __fmul_rn(__fdiv_rn(x, __fsub_rn(u, 1.0f)), logf(u));
}

__device__ __forceinline__ float xla_erfinv(float x) {
  float w = -xla_log1p(__fmul_rn(__fmul_rn(-1.0f, x), x));
  float p;
  if (w < 5.0f) {
    w = __fsub_rn(w, 2.5f);
    p = 2.81022636e-08f;
    p = __fadd_rn(__fmul_rn(p, w), 3.43273939e-07f);
    p = __fadd_rn(__fmul_rn(p, w), -3.5233877e-06f);
    p = __fadd_rn(__fmul_rn(p, w), -4.39150654e-06f);
    p = __fadd_rn(__fmul_rn(p, w), 0.00021858087f);
    p = __fadd_rn(__fmul_rn(p, w), -0.00125372503f);
    p = __fadd_rn(__fmul_rn(p, w), -0.00417768164f);
    p = __fadd_rn(__fmul_rn(p, w), 0.246640727f);
    p = __fadd_rn(__fmul_rn(p, w), 1.50140941f);
  } else {
    w = __fsub_rn(sqrtf(w), 3.0f);
    p = -0.000200214257f;
    p = __fadd_rn(__fmul_rn(p, w), 0.000100950558f);
    p = __fadd_rn(__fmul_rn(p, w), 0.00134934322f);
    p = __fadd_rn(__fmul_rn(p, w), -0.00367342844f);
    p = __fadd_rn(__fmul_rn(p, w), 0.00573950773f);
    p = __fadd_rn(__fmul_rn(p, w), -0.0076224613f);
    p = __fadd_rn(__fmul_rn(p, w), 0.00943887047f);
    p = __fadd_rn(__fmul_rn(p, w), 1.00167406f);
    p = __fadd_rn(__fmul_rn(p, w), 2.83297682f);
  }
  return __fmul_rn(p, x);
}

__device__ __forceinline__ float xla_tanh(float x) {
  float ax = fabsf(x);
  if (ax < 0.0004f) return x;
  float xc = fminf(fmaxf(x, -7.90531110763549805f), 7.90531110763549805f);
  float x2 = __fmul_rn(xc, xc);
  float p = -2.76076847742355e-16f;
  p = __fadd_rn(__fmul_rn(p, x2), 2.00018790482477e-13f);
  p = __fadd_rn(__fmul_rn(p, x2), -8.60467152213735e-11f);
  p = __fadd_rn(__fmul_rn(p, x2), 5.12229709037114e-08f);
  p = __fadd_rn(__fmul_rn(p, x2), 1.48572235717979e-05f);
  p = __fadd_rn(__fmul_rn(p, x2), 6.37261928875436e-04f);
  p = __fadd_rn(__fmul_rn(p, x2), 4.89352455891786e-03f);
  p = __fmul_rn(p, xc);
  float q = 1.19825839466702e-06f;
  q = __fadd_rn(__fmul_rn(q, x2), 1.18534705686654e-04f);
  q = __fadd_rn(__fmul_rn(q, x2), 2.26843463243900e-03f);
  q = __fadd_rn(__fmul_rn(q, x2), 4.89352518554385e-03f);
  return __fdiv_rn(p, q);
}

__device__ __forceinline__ float xla_logistic(float x) {
  return __fadd_rn(0.5f, __fmul_rn(0.5f, xla_tanh(__fmul_rn(0.5f, x))));
}

// bits -> N(0,1) exactly as jax.random.normal (float32 path)
__device__ __forceinline__ float bits_to_normal(u32 bits) {
  float u = __uint_as_float((bits >> 9) | 0x3F800000u) - 1.0f;   // [0,1)
  const float lo = __uint_as_float(0xBF7FFFFFu);                 // nextafter(-1,0)
  float v = __fadd_rn(__fmul_rn(u, 2.0f), lo);
  v = fmaxf(v, lo);
  return __fmul_rn(__uint_as_float(0x3FB504F3u) /*sqrt2*/, xla_erfinv(v));
}

// partitionable threefry random_bits: bits[j] = o0 ^ o1 of TF(key, 0, j)
__device__ __forceinline__ u32 jax_bits32(u32 k0, u32 k1, u32 j) {
  u32 o0, o1; threefry2x32(k0, k1, 0u, j, o0, o1);
  return o0 ^ o1;
}

// ---------------- float max encoding for atomicMax ----------------
__device__ __forceinline__ unsigned fenc(float f) {
  unsigned u = __float_as_uint(f);
  return (u & 0x80000000u) ? ~u : (u | 0x80000000u);
}
__device__ __forceinline__ float fdec(unsigned u) {
  return (u & 0x80000000u) ? __uint_as_float(u & 0x7FFFFFFFu) : __uint_as_float(~u);
}

__global__ void k_init_max() {
  if (threadIdx.x < 4) g_max[threadIdx.x] = fenc(-__int_as_float(0x7F800000));
  if (threadIdx.x == 0) g_tile = 0u;
}

__global__ void k_max(const float* __restrict__ x, int n, int slot) {
  float m = -__int_as_float(0x7F800000);
  for (int i = blockIdx.x * blockDim.x + threadIdx.x; i < n; i += gridDim.x * blockDim.x)
    m = fmaxf(m, x[i]);
#pragma unroll
  for (int o = 16; o; o >>= 1) m = fmaxf(m, __shfl_xor_sync(0xFFFFFFFFu, m, o));
  if ((threadIdx.x & 31) == 0) atomicMax(&g_max[slot], fenc(m));
}

// quant(x, 8, 1.0) for weights
__device__ __forceinline__ float quant_w(float x) {
  float xs = fminf(fmaxf(x, -0.9921875f), 0.9921875f);
  return __fmul_rn(__fdiv_rn(rintf(__fmul_rn(xs, 128.0f)), 128.0f), 1.0f);
}

// Weff[k][o][m] = quant(W[m][k][o]) + normal(ctr = src linear)*wmax*0.1
template<int K>
__global__ void k_build_w(const float* __restrict__ W, int n, u32 kk0, u32 kk1,
                          int slot, int which_hh) {
  int j = blockIdx.x * blockDim.x + threadIdx.x;   // dst linear [K][O][MPL]
  if (j >= n) return;
  float* dst = which_hh ? g_weff_hh : g_weff_ih;
  float wmax = fdec(g_max[slot]);
  int k = j >> 14;                 // O_DIM*MPL = 16384
  int rem = j & 16383;
  int o = rem >> 2, m = rem & 3;
  u32 src = (u32)((m * K + k) * O_DIM + o);        // source linear = PRNG counter
  float nr = bits_to_normal(jax_bits32(kk0, kk1, src));
  dst[j] = __fadd_rn(quant_w(W[src]), __fmul_rn(__fmul_rn(nr, wmax), 0.1f));
}

// biases: bq and nb separate so the (mm + bq) + nb add order matches reference
__global__ void k_build_b(const float* __restrict__ Bsrc, int n, u32 kk0, u32 kk1,
                          int slot, int which_hh) {
  int j = blockIdx.x * blockDim.x + threadIdx.x;
  if (j >= n) return;
  float* bq = which_hh ? g_bq_hh : g_bq_ih;
  float* nb = which_hh ? g_nb_hh : g_nb_ih;
  float bmax = fdec(g_max[slot]);
  bq[j] = quant_w(Bsrc[j]);
  nb[j] = __fmul_rn(__fmul_rn(bits_to_normal(jax_bits32(kk0, kk1, (u32)j)), bmax), 0.1f);
}

// activation -> 4-bit plane nibble
__global__ void k_nib(const float* __restrict__ x, uint8_t* __restrict__ nib, int n,
                      const float* __restrict__ aP, const float* __restrict__ offP) {
  int i = blockIdx.x * blockDim.x + threadIdx.x;
  if (i >= n) return;
  float a = *aP, off = *offP;
  float t = __fdiv_rn(__fadd_rn(fminf(fmaxf(x[i], -a), a), off), __fmul_rn(a, 2.0f));
  float v = rintf(__fmul_rn(15.0f, t));
  nib[i] = (uint8_t)(((int)v) & 15);
}

// ---------------- persistent GEMM (both branches, one kernel) ----------------
// fma.rn.f32x2 lanes = plane pairs; per-lane acc = rn(w*mask + acc), mask in
// {0,1} via 16-entry LUT -> bit-identical to sequential ascending-k fp32 chain.
#define BM 64
#define BN 64
#define KC 32
#define N_TILES_HH 4096
#define N_TILES_ALL 8192
#define GRID_GEMM 296

__device__ __forceinline__ void fma2(u64 &acc, u64 w, u64 m) {
  asm volatile("fma.rn.f32x2 %0, %1, %2, %0;" : "+l"(acc) : "l"(w), "l"(m));
}
__device__ __forceinline__ void lds_v2u64(u64 &a, u64 &b, u32 addr) {
  asm volatile("ld.shared.v2.b64 {%0,%1}, [%2];" : "=l"(a), "=l"(b) : "r"(addr));
}
__device__ __forceinline__ void unpack2(u64 v, float &lo, float &hi) {
  u32 l, h;
  asm volatile("mov.b64 {%0,%1}, %2;" : "=r"(l), "=r"(h) : "l"(v));
  lo = __uint_as_float(l); hi = __uint_as_float(h);
}

__launch_bounds__(256, 2)
__global__ void k_gemm_all(const float* __restrict__ a1P, const float* __restrict__ a11P) {
  __shared__ __align__(16) float sW[KC][BN * MPL];   // 32 KB, [k][o*4+m]
  __shared__ u32 sA[BM][KC / 4];                     // 2 KB
  __shared__ __align__(16) float4 sLut[16];
  __shared__ u32 sTile;

  int tid = threadIdx.x;
  if (tid < 16)
    sLut[tid] = make_float4((float)((tid >> 3) & 1), (float)((tid >> 2) & 1),
                            (float)((tid >> 1) & 1), (float)(tid & 1));
  int tx = tid & 15, ty = tid >> 4;
  int rowBase = ty * 4;

  u32 sWb = (u32)__cvta_generic_to_shared(sW);
  u32 sLb = (u32)__cvta_generic_to_shared(sLut);

  while (true) {
    if (tid == 0) sTile = atomicAdd(&g_tile, 1u);
    __syncthreads();                 // also orders sLut init / prev-tile smem reuse
    u32 t = sTile;
    if (t >= N_TILES_ALL) break;

    // hh tiles first (big), then ih (small) for a short ragged tail
    bool hh = (t < N_TILES_HH);
    u32 t2 = hh ? t : (t - N_TILES_HH);
    int K = hh ? H_DIM : I_DIM;
    const float* __restrict__ Wg = hh ? g_weff_hh : g_weff_ih;   // [K][O][MPL]
    const float* __restrict__ bq = hh ? g_bq_hh : g_bq_ih;
    const float* __restrict__ nb = hh ? g_nb_hh : g_nb_ih;
    const uint8_t* __restrict__ nibp = hh ? g_nib_hx : g_nib_in;
    float* __restrict__ gout = hh ? g_gates2 : g_gates1;
    float a = hh ? *a11P : *a1P;

    int ob = (int)(t2 & 63) * BN;
    int bb = (int)(t2 >> 6) * BM;

    u64 acc[4][4][2];   // [row][col][plane-pair]
#pragma unroll
    for (int r = 0; r < 4; ++r)
#pragma unroll
      for (int c = 0; c < 4; ++c) { acc[r][c][0] = 0ull; acc[r][c][1] = 0ull; }

    for (int k0 = 0; k0 < K; k0 += KC) {
#pragma unroll
      for (int tt = 0; tt < 2; ++tt) {            // A tile: 64 rows x 8 u32
        int idx = tid + tt * 256;
        int r = idx >> 3, k4 = idx & 7;
        sA[r][k4] = *(const u32*)(nibp + (size_t)(bb + r) * K + k0 + k4 * 4);
      }
#pragma unroll
      for (int tt = 0; tt < 8; ++tt) {            // W tile: 2048 contiguous float4
        int idx = tid + tt * 256;
        int k = idx >> 6, w4 = idx & 63;
        *(float4*)&sW[k][w4 * 4] =
            *(const float4*)(Wg + ((size_t)(k0 + k) * O_DIM + ob) * MPL + w4 * 4);
      }
      __syncthreads();

#pragma unroll
      for (int k4 = 0; k4 < KC / 4; ++k4) {
        u32 av[4];
#pragma unroll
        for (int r = 0; r < 4; ++r) av[r] = sA[rowBase + r][k4];
#pragma unroll
        for (int s = 0; s < 4; ++s) {
          int k = k4 * 4 + s;
          u64 mk[4][2];
#pragma unroll
          for (int r = 0; r < 4; ++r) {
            u32 ad = sLb + (((av[r] >> (8 * s)) & 15u) << 4);
            lds_v2u64(mk[r][0], mk[r][1], ad);
          }
#pragma unroll
          for (int c = 0; c < 4; ++c) {
            u64 w0, w1;
            u32 wad = sWb + (u32)(k * (BN * MPL * 4)) + (u32)((tx + 16 * c) * 16);
            lds_v2u64(w0, w1, wad);
#pragma unroll
            for (int r = 0; r < 4; ++r) {
              fma2(acc[r][c][0], w0, mk[r][0]);
              fma2(acc[r][c][1], w1, mk[r][1]);
            }
          }
        }
      }
      __syncthreads();
    }

    // epilogue: threshold per plane, beta-recombine, scale -> its own buffer
    float twoa = __fmul_rn(a, 2.0f);
    const float beta[MPL] = {8.0f / 15.0f, 4.0f / 15.0f, 2.0f / 15.0f, 1.0f / 15.0f};
#pragma unroll
    for (int r = 0; r < 4; ++r) {
#pragma unroll
      for (int c = 0; c < 4; ++c) {
        int b = bb + rowBase + r, o = ob + tx + 16 * c;
        float sv[4];
        unpack2(acc[r][c][0], sv[0], sv[1]);
        unpack2(acc[r][c][1], sv[2], sv[3]);
        float p = 0.0f;
#pragma unroll
        for (int m = 0; m < MPL; ++m) {
          float s = __fadd_rn(__fadd_rn(sv[m], bq[m * O_DIM + o]), nb[m * O_DIM + o]);
          p = __fadd_rn(p, (s > 0.5f) ? beta[m] : 0.0f);
        }
        gout[(size_t)b * O_DIM + o] = __fsub_rn(__fmul_rn(p, twoa), a);
      }
    }
  }
}

// ---------------- quantized LSTM pointwise tail ----------------
__device__ __forceinline__ float pactf(float x, float a) { return fminf(fmaxf(x, -a), a); }
__device__ __forceinline__ float quant8(float x, float r) {
  float xs = __fdiv_rn(x, r);
  xs = fminf(fmaxf(xs, -0.9921875f), 0.9921875f);
  return __fmul_rn(__fdiv_rn(rintf(__fmul_rn(xs, 128.0f)), 128.0f), r);
}

__global__ void k_lstm(const float* __restrict__ cx, float* __restrict__ out,
                       const float* a3, const float* a4, const float* a5, const float* a6,
                       const float* a7, const float* a8, const float* a9, const float* a10,
                       const float* a11) {
  int idx = blockIdx.x * blockDim.x + threadIdx.x;
  if (idx >= B_DIM * H_DIM) return;
  int b = idx >> 10, h = idx & (H_DIM - 1);
  const float* g1 = g_gates1 + (size_t)b * O_DIM;
  const float* g2 = g_gates2 + (size_t)b * O_DIM;
  // gates = part1 + part2 (single rn add, matching reference)
  float gi = __fadd_rn(g1[h],        g2[h]);
  float gj = __fadd_rn(g1[h + 1024], g2[h + 1024]);
  float gf = __fadd_rn(g1[h + 2048], g2[h + 2048]);
  float go = __fadd_rn(g1[h + 3072], g2[h + 3072]);

  float v3 = *a3, v4 = *a4, v5 = *a5, v6 = *a6, v7 = *a7, v8 = *a8, v9 = *a9,
        v10 = *a10, v11 = *a11;
  float fg  = quant8(pactf(xla_logistic(gf), v3), v3);
  float ig  = quant8(pactf(xla_logistic(gi), v4), v4);
  float act = quant8(pactf(xla_tanh(gj), v5), v5);
  float og  = quant8(pactf(xla_logistic(go), v6), v6);
  float gated = quant8(pactf(__fmul_rn(cx[idx], fg), v7), v7);
  float actin = quant8(pactf(__fmul_rn(ig, act), v8), v8);
  float newc  = quant8(pactf(__fadd_rn(gated, actin), v9), v9);
  float actc  = quant8(pactf(xla_tanh(newc), v10), v10);
  float newh  = quant8(pactf(__fmul_rn(actc, og), v11), v11);
  out[idx] = newh;
  out[(size_t)B_DIM * H_DIM + idx] = newc;
}

// ---------------- host side ----------------
static void split2(const u32 k[2], u32 ka[2], u32 kb[2]) {
  threefry2x32(k[0], k[1], 0u, 0u, ka[0], ka[1]);
  threefry2x32(k[0], k[1], 0u, 1u, kb[0], kb[1]);
}

extern "C" void kernel_launch(void* const* d_in, const int* in_sizes, int n_in,
                              void* d_out, int out_size) {
  const float* input = (const float*)d_in[0];
  const float* hx    = (const float*)d_in[1];
  const float* cx    = (const float*)d_in[2];
  const float* wih   = (const float*)d_in[3];
  const float* whh   = (const float*)d_in[4];
  const float* bih   = (const float*)d_in[5];
  const float* bhh   = (const float*)d_in[6];
  const float* a1  = (const float*)d_in[7];
  const float* a3  = (const float*)d_in[8];
  const float* a4  = (const float*)d_in[9];
  const float* a5  = (const float*)d_in[10];
  const float* a6  = (const float*)d_in[11];
  const float* a7  = (const float*)d_in[12];
  const float* a8  = (const float*)d_in[13];
  const float* a9  = (const float*)d_in[14];
  const float* a10 = (const float*)d_in[15];
  const float* a11 = (const float*)d_in[16];

  u32 root[2] = {0u, 42u}, K1[2], K2[2], KW1[2], KB1[2], KW2[2], KB2[2];
  split2(root, K1, K2);
  split2(K1, KW1, KB1);
  split2(K2, KW2, KB2);

  const int n_wih = MPL * I_DIM * O_DIM;   // 4,194,304
  const int n_whh = MPL * H_DIM * O_DIM;   // 16,777,216
  const int n_b   = MPL * O_DIM;           // 16,384

  k_init_max<<<1, 32>>>();
  k_max<<<512, 256>>>(wih, n_wih, 0);
  k_max<<<512, 256>>>(whh, n_whh, 1);
  k_max<<<64, 256>>>(bih, n_b, 2);
  k_max<<<64, 256>>>(bhh, n_b, 3);

  k_build_w<I_DIM><<<(n_wih + 255) / 256, 256>>>(wih, n_wih, KW1[0], KW1[1], 0, 0);
  k_build_w<H_DIM><<<(n_whh + 255) / 256, 256>>>(whh, n_whh, KW2[0], KW2[1], 1, 1);
  k_build_b<<<(n_b + 255) / 256, 256>>>(bih, n_b, KB1[0], KB1[1], 2, 0);
  k_build_b<<<(n_b + 255) / 256, 256>>>(bhh, n_b, KB2[0], KB2[1], 3, 1);

  {
    uint8_t* nin; cudaGetSymbolAddress((void**)&nin, g_nib_in);
    uint8_t* nhx; cudaGetSymbolAddress((void**)&nhx, g_nib_hx);
    k_nib<<<(B_DIM * I_DIM + 255) / 256, 256>>>(input, nin, B_DIM * I_DIM, a1, a1);
    k_nib<<<(B_DIM * H_DIM + 255) / 256, 256>>>(hx, nhx, B_DIM * H_DIM, a11, a1);
  }

  // one persistent kernel: hh tiles (0..4095) then ih tiles (4096..8191)
  k_gemm_all<<<GRID_GEMM, 256>>>(a1, a11);

  k_lstm<<<(B_DIM * H_DIM + 255) / 256, 256>>>(cx, (float*)d_out,
                                               a3, a4, a5, a6, a7, a8, a9, a10, a11);
}